// round 3
// baseline (speedup 1.0000x reference)
#include <cuda_runtime.h>
#include <math.h>

#define BB 2
#define SS 2048
#define HH 16
#define DH 64
#define DM 1024
#define MTOT (BB*SS)   // 4096

// Scratch (device globals are the sanctioned scratch mechanism)
__device__ float g_Q[BB*HH*SS*DH];   // [B,H,S,64]
__device__ float g_K[BB*HH*SS*DH];
__device__ float g_V[BB*HH*SS*DH];
__device__ float g_A[MTOT*DM];       // attention concat output [B,S,1024]

// ---------------------------------------------------------------------------
// Fused QKV projection GEMM: y = x @ w, written head-major into g_Q/g_K/g_V.
// BM=BN=128, BK=8, 256 threads, 8x8 microtile.  (smem: 2*8*128*4 = 8 KB, static OK)
// ---------------------------------------------------------------------------
__global__ __launch_bounds__(256)
void qkv_gemm(const float* __restrict__ x,
              const float* __restrict__ wq,
              const float* __restrict__ wk,
              const float* __restrict__ wv) {
    const int which = blockIdx.z;
    const float* __restrict__ w = (which == 0) ? wq : (which == 1) ? wk : wv;
    float* __restrict__ dst = (which == 0) ? g_Q : (which == 1) ? g_K : g_V;

    __shared__ float As[8][128];
    __shared__ float Bs[8][128];

    const int tid  = threadIdx.x;
    const int tCol = tid & 15;        // 0..15
    const int tRow = tid >> 4;        // 0..15
    const int rowBase = blockIdx.y * 128;
    const int colBase = blockIdx.x * 128;

    const int aRow = tid >> 1;        // 0..127
    const int aCol = (tid & 1) * 4;   // 0 or 4
    const int bRow = tid >> 5;        // 0..7
    const int bCol = (tid & 31) * 4;  // 0..124

    float acc[8][8];
    #pragma unroll
    for (int i = 0; i < 8; i++)
        #pragma unroll
        for (int j = 0; j < 8; j++) acc[i][j] = 0.f;

    for (int k0 = 0; k0 < DM; k0 += 8) {
        float4 a = *(const float4*)&x[(rowBase + aRow) * DM + k0 + aCol];
        As[aCol + 0][aRow] = a.x;
        As[aCol + 1][aRow] = a.y;
        As[aCol + 2][aRow] = a.z;
        As[aCol + 3][aRow] = a.w;
        float4 b = *(const float4*)&w[(k0 + bRow) * DM + colBase + bCol];
        *(float4*)&Bs[bRow][bCol] = b;
        __syncthreads();
        #pragma unroll
        for (int k = 0; k < 8; k++) {
            float4 a0 = *(const float4*)&As[k][tRow * 8];
            float4 a1 = *(const float4*)&As[k][tRow * 8 + 4];
            float4 b0 = *(const float4*)&Bs[k][tCol * 8];
            float4 b1 = *(const float4*)&Bs[k][tCol * 8 + 4];
            float ra[8] = {a0.x, a0.y, a0.z, a0.w, a1.x, a1.y, a1.z, a1.w};
            float rb[8] = {b0.x, b0.y, b0.z, b0.w, b1.x, b1.y, b1.z, b1.w};
            #pragma unroll
            for (int i = 0; i < 8; i++)
                #pragma unroll
                for (int j = 0; j < 8; j++)
                    acc[i][j] = fmaf(ra[i], rb[j], acc[i][j]);
        }
        __syncthreads();
    }

    // Store head-major: row r -> (b, s); col c -> (h, d)
    const int c0 = colBase + tCol * 8;
    const int h  = c0 / DH;
    const int d0 = c0 % DH;           // 8-col run never crosses a head (8 | 64)
    #pragma unroll
    for (int i = 0; i < 8; i++) {
        const int r  = rowBase + tRow * 8 + i;
        const int bb = r / SS, sp = r % SS;
        float* p = &dst[(((bb * HH + h) * SS) + sp) * DH + d0];
        *(float4*)(p)     = make_float4(acc[i][0], acc[i][1], acc[i][2], acc[i][3]);
        *(float4*)(p + 4) = make_float4(acc[i][4], acc[i][5], acc[i][6], acc[i][7]);
    }
}

// ---------------------------------------------------------------------------
// Flash attention: BQ=64 q-rows, BK=64 kv-cols, d=64. 128 threads.
// Thread (ty 0..15, tx 0..7): 4 q-rows x 8 cols microtile.
// Shared memory is DYNAMIC (66.5 KB > 48 KB static limit).
// Layout: Qs[64][65] | Ks[64][65] | Vs[64][65] | Ps[64][65]
// ---------------------------------------------------------------------------
#define BQ 64
#define BKT 64
#define LDP (DH + 1)                 // 65: padded row stride
#define FA_SMEM_FLOATS (4 * BQ * LDP)
#define FA_SMEM_BYTES  (FA_SMEM_FLOATS * sizeof(float))

__global__ __launch_bounds__(128)
void flash_attn() {
    extern __shared__ float sm[];
    float* Qs = sm;                      // [BQ][LDP]
    float* Ks = Qs + BQ * LDP;           // [BKT][LDP]
    float* Vs = Ks + BKT * LDP;          // [BKT][LDP]
    float* Ps = Vs + BKT * LDP;          // [BQ][LDP]  (BKT+1 cols used)

    const int qt = blockIdx.x;   // 0..31
    const int bh = blockIdx.y;   // 0..31
    const float* __restrict__ Qp = g_Q + (size_t)bh * SS * DH;
    const float* __restrict__ Kp = g_K + (size_t)bh * SS * DH;
    const float* __restrict__ Vp = g_V + (size_t)bh * SS * DH;

    const int tid = threadIdx.x;
    const int tx = tid & 7;      // 0..7
    const int ty = tid >> 3;     // 0..15

    // Load Q tile (64x64)
    for (int t = tid; t < BQ * DH / 4; t += 128) {
        int r = t >> 4;             // 16 float4 per row
        int c = (t & 15) * 4;
        float4 v = *(const float4*)&Qp[(qt * BQ + r) * DH + c];
        Qs[r * LDP + c] = v.x; Qs[r * LDP + c + 1] = v.y;
        Qs[r * LDP + c + 2] = v.z; Qs[r * LDP + c + 3] = v.w;
    }

    float o[4][8];
    float m[4], l[4];
    #pragma unroll
    for (int i = 0; i < 4; i++) {
        m[i] = -1e30f; l[i] = 0.f;
        #pragma unroll
        for (int j = 0; j < 8; j++) o[i][j] = 0.f;
    }

    for (int kt = 0; kt < SS / BKT; kt++) {
        __syncthreads();   // prior PV reads of Ks/Vs/Ps done before overwrite
        for (int t = tid; t < BKT * DH / 4; t += 128) {
            int r = t >> 4;
            int c = (t & 15) * 4;
            float4 kv = *(const float4*)&Kp[(kt * BKT + r) * DH + c];
            Ks[r * LDP + c] = kv.x; Ks[r * LDP + c + 1] = kv.y;
            Ks[r * LDP + c + 2] = kv.z; Ks[r * LDP + c + 3] = kv.w;
            float4 vv = *(const float4*)&Vp[(kt * BKT + r) * DH + c];
            Vs[r * LDP + c] = vv.x; Vs[r * LDP + c + 1] = vv.y;
            Vs[r * LDP + c + 2] = vv.z; Vs[r * LDP + c + 3] = vv.w;
        }
        __syncthreads();

        // S = Q K^T (4x8 per thread)
        float s[4][8];
        #pragma unroll
        for (int i = 0; i < 4; i++)
            #pragma unroll
            for (int j = 0; j < 8; j++) s[i][j] = 0.f;

        for (int kk = 0; kk < DH; kk++) {
            float q[4], k[8];
            #pragma unroll
            for (int i = 0; i < 4; i++) q[i] = Qs[(ty * 4 + i) * LDP + kk];
            #pragma unroll
            for (int j = 0; j < 8; j++) k[j] = Ks[(tx * 8 + j) * LDP + kk];
            #pragma unroll
            for (int i = 0; i < 4; i++)
                #pragma unroll
                for (int j = 0; j < 8; j++)
                    s[i][j] = fmaf(q[i], k[j], s[i][j]);
        }

        // online softmax per row (reduce over tx group of 8 lanes)
        #pragma unroll
        for (int i = 0; i < 4; i++) {
            float mx = -1e30f;
            #pragma unroll
            for (int j = 0; j < 8; j++) {
                s[i][j] *= 0.125f;              // 1/sqrt(64)
                mx = fmaxf(mx, s[i][j]);
            }
            #pragma unroll
            for (int off = 4; off >= 1; off >>= 1)
                mx = fmaxf(mx, __shfl_xor_sync(0xffffffffu, mx, off, 8));
            float mnew = fmaxf(m[i], mx);
            float alpha = __expf(m[i] - mnew);
            float rowsum = 0.f;
            #pragma unroll
            for (int j = 0; j < 8; j++) {
                float p = __expf(s[i][j] - mnew);
                Ps[(ty * 4 + i) * LDP + tx * 8 + j] = p;
                rowsum += p;
            }
            #pragma unroll
            for (int off = 4; off >= 1; off >>= 1)
                rowsum += __shfl_xor_sync(0xffffffffu, rowsum, off, 8);
            l[i] = l[i] * alpha + rowsum;
            m[i] = mnew;
            #pragma unroll
            for (int j = 0; j < 8; j++) o[i][j] *= alpha;
        }
        __syncthreads();   // Ps visible

        // O += P @ V
        for (int j = 0; j < BKT; j++) {
            float p[4], v[8];
            #pragma unroll
            for (int i = 0; i < 4; i++) p[i] = Ps[(ty * 4 + i) * LDP + j];
            #pragma unroll
            for (int c = 0; c < 8; c++) v[c] = Vs[j * LDP + tx * 8 + c];
            #pragma unroll
            for (int i = 0; i < 4; i++)
                #pragma unroll
                for (int c = 0; c < 8; c++)
                    o[i][c] = fmaf(p[i], v[c], o[i][c]);
        }
    }

    // normalize + store concat layout [B,S,H*64]
    const int b = bh / HH, h = bh % HH;
    #pragma unroll
    for (int i = 0; i < 4; i++) {
        const int srow = qt * BQ + ty * 4 + i;
        const float inv = 1.f / l[i];
        float* p = &g_A[((size_t)(b * SS + srow)) * DM + h * DH + tx * 8];
        *(float4*)(p)     = make_float4(o[i][0] * inv, o[i][1] * inv, o[i][2] * inv, o[i][3] * inv);
        *(float4*)(p + 4) = make_float4(o[i][4] * inv, o[i][5] * inv, o[i][6] * inv, o[i][7] * inv);
    }
}

// ---------------------------------------------------------------------------
// Output projection: out = g_A @ wo + bo, row-major into d_out.
// ---------------------------------------------------------------------------
__global__ __launch_bounds__(256)
void out_gemm(const float* __restrict__ wo,
              const float* __restrict__ bo,
              float* __restrict__ out) {
    __shared__ float As[8][128];
    __shared__ float Bs[8][128];

    const int tid  = threadIdx.x;
    const int tCol = tid & 15;
    const int tRow = tid >> 4;
    const int rowBase = blockIdx.y * 128;
    const int colBase = blockIdx.x * 128;

    const int aRow = tid >> 1;
    const int aCol = (tid & 1) * 4;
    const int bRow = tid >> 5;
    const int bCol = (tid & 31) * 4;

    float acc[8][8];
    #pragma unroll
    for (int i = 0; i < 8; i++)
        #pragma unroll
        for (int j = 0; j < 8; j++) acc[i][j] = 0.f;

    for (int k0 = 0; k0 < DM; k0 += 8) {
        float4 a = *(const float4*)&g_A[(size_t)(rowBase + aRow) * DM + k0 + aCol];
        As[aCol + 0][aRow] = a.x;
        As[aCol + 1][aRow] = a.y;
        As[aCol + 2][aRow] = a.z;
        As[aCol + 3][aRow] = a.w;
        float4 b = *(const float4*)&wo[(k0 + bRow) * DM + colBase + bCol];
        *(float4*)&Bs[bRow][bCol] = b;
        __syncthreads();
        #pragma unroll
        for (int k = 0; k < 8; k++) {
            float4 a0 = *(const float4*)&As[k][tRow * 8];
            float4 a1 = *(const float4*)&As[k][tRow * 8 + 4];
            float4 b0 = *(const float4*)&Bs[k][tCol * 8];
            float4 b1 = *(const float4*)&Bs[k][tCol * 8 + 4];
            float ra[8] = {a0.x, a0.y, a0.z, a0.w, a1.x, a1.y, a1.z, a1.w};
            float rb[8] = {b0.x, b0.y, b0.z, b0.w, b1.x, b1.y, b1.z, b1.w};
            #pragma unroll
            for (int i = 0; i < 8; i++)
                #pragma unroll
                for (int j = 0; j < 8; j++)
                    acc[i][j] = fmaf(ra[i], rb[j], acc[i][j]);
        }
        __syncthreads();
    }

    const int c0 = colBase + tCol * 8;
    float bias[8];
    #pragma unroll
    for (int j = 0; j < 8; j++) bias[j] = bo[c0 + j];

    #pragma unroll
    for (int i = 0; i < 8; i++) {
        const int r = rowBase + tRow * 8 + i;
        float* p = &out[(size_t)r * DM + c0];
        *(float4*)(p)     = make_float4(acc[i][0] + bias[0], acc[i][1] + bias[1],
                                        acc[i][2] + bias[2], acc[i][3] + bias[3]);
        *(float4*)(p + 4) = make_float4(acc[i][4] + bias[4], acc[i][5] + bias[5],
                                        acc[i][6] + bias[6], acc[i][7] + bias[7]);
    }
}

extern "C" void kernel_launch(void* const* d_in, const int* in_sizes, int n_in,
                              void* d_out, int out_size) {
    const float* x  = (const float*)d_in[0];
    const float* wq = (const float*)d_in[1];
    const float* wk = (const float*)d_in[2];
    const float* wv = (const float*)d_in[3];
    const float* wo = (const float*)d_in[4];
    const float* bo = (const float*)d_in[5];
    float* out = (float*)d_out;

    // Opt-in to >48KB dynamic smem for flash_attn. Host-side attribute set:
    // no allocation, no sync, no graph nodes — capture-safe and idempotent.
    cudaFuncSetAttribute(flash_attn,
                         cudaFuncAttributeMaxDynamicSharedMemorySize,
                         FA_SMEM_BYTES);

    dim3 gProj(DM / 128, MTOT / 128, 3);   // 8 x 32 x 3
    qkv_gemm<<<gProj, 256>>>(x, wq, wk, wv);

    dim3 gAttn(SS / BQ, BB * HH);          // 32 x 32
    flash_attn<<<gAttn, 128, FA_SMEM_BYTES>>>();

    dim3 gOut(DM / 128, MTOT / 128);       // 8 x 32
    out_gemm<<<gOut, 256>>>(wo, bo, out);
}

// round 4
// speedup vs baseline: 3.4716x; 3.4716x over previous
#include <cuda_runtime.h>

#define BB 2
#define SS 2048
#define HH 16
#define DH 64
#define DM 1024
#define MTOT (BB*SS)   // 4096

// Scratch (device globals are the sanctioned scratch mechanism)
__device__ float g_Q[BB*HH*SS*DH];   // [B,H,S,64]
__device__ float g_K[BB*HH*SS*DH];
__device__ float g_V[BB*HH*SS*DH];
__device__ float g_A[MTOT*DM];       // attention concat output [B,S,1024]

// ---------------------------------------------------------------------------
// tf32 helpers
// ---------------------------------------------------------------------------
__device__ __forceinline__ unsigned f2tf(float f) {
    unsigned u;
    asm("cvt.rna.tf32.f32 %0, %1;" : "=r"(u) : "f"(f));
    return u;
}

// D += A @ B, m16n8k8, A row-major frag, B "col-major" frag (indexed [k][n])
__device__ __forceinline__ void mma8(float* d, const unsigned* a, const unsigned* b) {
    asm volatile(
        "mma.sync.aligned.m16n8k8.row.col.f32.tf32.tf32.f32 "
        "{%0,%1,%2,%3},{%4,%5,%6,%7},{%8,%9},{%0,%1,%2,%3};"
        : "+f"(d[0]), "+f"(d[1]), "+f"(d[2]), "+f"(d[3])
        : "r"(a[0]), "r"(a[1]), "r"(a[2]), "r"(a[3]), "r"(b[0]), "r"(b[1]));
}

// ---------------------------------------------------------------------------
// Tensor-core GEMM: C = A @ B (+bias). 128x128x32 tiles, 256 thr, 8 warps.
// MODE 0: qkv — A=x, B selected by blockIdx.z among {wq,wk,wv}, store
//         head-major into g_Q/g_K/g_V.
// MODE 1: out — A=g_A (global), B=wo, bias added, row-major into out param.
// Smem strides 36 / 132 (= 4 mod 32 -> conflict-free fragment loads).
// ---------------------------------------------------------------------------
#define GLDA 36
#define GLDB 132

template<int MODE>
__global__ __launch_bounds__(256)
void gemm_tc(const float* __restrict__ Ain,
             const float* __restrict__ B0,
             const float* __restrict__ B1,
             const float* __restrict__ B2,
             const float* __restrict__ bias,
             float* __restrict__ outp) {
    __shared__ unsigned As[128 * GLDA];
    __shared__ unsigned Bs[32 * GLDB];

    const int tid = threadIdx.x, lane = tid & 31, warp = tid >> 5;
    const int wm = (warp & 1) * 64, wn = (warp >> 1) * 32;
    const int rowBase = blockIdx.y * 128, colBase = blockIdx.x * 128;

    const float* __restrict__ A = (MODE == 0) ? Ain : g_A;
    const float* __restrict__ B =
        (MODE == 0) ? (blockIdx.z == 0 ? B0 : blockIdx.z == 1 ? B1 : B2) : B0;

    float acc[4][4][4];
    #pragma unroll
    for (int mt = 0; mt < 4; mt++)
        #pragma unroll
        for (int nt = 0; nt < 4; nt++)
            #pragma unroll
            for (int i = 0; i < 4; i++) acc[mt][nt][i] = 0.f;

    for (int kb = 0; kb < DM; kb += 32) {
        #pragma unroll
        for (int it = 0; it < 4; it++) {
            int idx = tid + it * 256;
            int r = idx >> 3, cv = (idx & 7) * 4;
            float4 a = *(const float4*)&A[(size_t)(rowBase + r) * DM + kb + cv];
            As[r * GLDA + cv + 0] = f2tf(a.x);
            As[r * GLDA + cv + 1] = f2tf(a.y);
            As[r * GLDA + cv + 2] = f2tf(a.z);
            As[r * GLDA + cv + 3] = f2tf(a.w);
            int rb = idx >> 5, cb = (idx & 31) * 4;
            float4 b = *(const float4*)&B[(size_t)(kb + rb) * DM + colBase + cb];
            Bs[rb * GLDB + cb + 0] = f2tf(b.x);
            Bs[rb * GLDB + cb + 1] = f2tf(b.y);
            Bs[rb * GLDB + cb + 2] = f2tf(b.z);
            Bs[rb * GLDB + cb + 3] = f2tf(b.w);
        }
        __syncthreads();

        #pragma unroll
        for (int ks = 0; ks < 4; ks++) {
            const int kk = ks * 8;
            unsigned af[4][4], bf[4][2];
            #pragma unroll
            for (int mt = 0; mt < 4; mt++) {
                int r = wm + mt * 16 + (lane >> 2);
                af[mt][0] = As[r * GLDA + kk + (lane & 3)];
                af[mt][1] = As[(r + 8) * GLDA + kk + (lane & 3)];
                af[mt][2] = As[r * GLDA + kk + 4 + (lane & 3)];
                af[mt][3] = As[(r + 8) * GLDA + kk + 4 + (lane & 3)];
            }
            #pragma unroll
            for (int nt = 0; nt < 4; nt++) {
                int c = wn + nt * 8 + (lane >> 2);
                bf[nt][0] = Bs[(kk + (lane & 3)) * GLDB + c];
                bf[nt][1] = Bs[(kk + 4 + (lane & 3)) * GLDB + c];
            }
            #pragma unroll
            for (int mt = 0; mt < 4; mt++)
                #pragma unroll
                for (int nt = 0; nt < 4; nt++)
                    mma8(acc[mt][nt], af[mt], bf[nt]);
        }
        __syncthreads();
    }

    // Epilogue. C frag: (row=lane>>2, col=(lane&3)*2), (row+8) pair.
    if (MODE == 0) {
        float* __restrict__ dst =
            (blockIdx.z == 0) ? g_Q : (blockIdx.z == 1) ? g_K : g_V;
        #pragma unroll
        for (int mt = 0; mt < 4; mt++)
            #pragma unroll
            for (int nt = 0; nt < 4; nt++) {
                int r0 = rowBase + wm + mt * 16 + (lane >> 2);
                int c0 = colBase + wn + nt * 8 + (lane & 3) * 2;
                int h = c0 >> 6, d = c0 & 63;
                int bb = r0 >> 11, s = r0 & 2047;
                float* p = &dst[(((size_t)(bb * HH + h) * SS) + s) * DH + d];
                *(float2*)p = make_float2(acc[mt][nt][0], acc[mt][nt][1]);
                float* p2 = &dst[(((size_t)(bb * HH + h) * SS) + s + 8) * DH + d];
                *(float2*)p2 = make_float2(acc[mt][nt][2], acc[mt][nt][3]);
            }
    } else {
        #pragma unroll
        for (int mt = 0; mt < 4; mt++)
            #pragma unroll
            for (int nt = 0; nt < 4; nt++) {
                int r0 = rowBase + wm + mt * 16 + (lane >> 2);
                int c0 = colBase + wn + nt * 8 + (lane & 3) * 2;
                float2 bi = *(const float2*)&bias[c0];
                *(float2*)&outp[(size_t)r0 * DM + c0] =
                    make_float2(acc[mt][nt][0] + bi.x, acc[mt][nt][1] + bi.y);
                *(float2*)&outp[(size_t)(r0 + 8) * DM + c0] =
                    make_float2(acc[mt][nt][2] + bi.x, acc[mt][nt][3] + bi.y);
            }
    }
}

// ---------------------------------------------------------------------------
// Flash attention on tensor cores. 64 q-rows x 64 kv tiles, d=64.
// 4 warps; warp w owns q-rows [16w, 16w+16). All mma m16n8k8 tf32.
// Smem (dynamic, tf32 words): Qs|Ks|Vs|Ps, each 64 x 68 (stride 68 = 4 mod 32).
// ---------------------------------------------------------------------------
#define LDF 68
#define FA_SMEM_BYTES (4 * 64 * LDF * 4)

__global__ __launch_bounds__(128)
void flash_attn_tc() {
    extern __shared__ unsigned smu[];
    unsigned* Qs = smu;
    unsigned* Ks = Qs + 64 * LDF;
    unsigned* Vs = Ks + 64 * LDF;
    unsigned* Ps = Vs + 64 * LDF;

    const int qt = blockIdx.x;   // 0..31
    const int bh = blockIdx.y;   // 0..31
    const float* __restrict__ Qp = g_Q + (size_t)bh * SS * DH;
    const float* __restrict__ Kp = g_K + (size_t)bh * SS * DH;
    const float* __restrict__ Vp = g_V + (size_t)bh * SS * DH;

    const int tid = threadIdx.x, lane = tid & 31, warp = tid >> 5;

    // Load Q tile once, fold in 1/sqrt(64) scale.
    for (int idx = tid; idx < 64 * DH / 4; idx += 128) {
        int r = idx >> 4, cv = (idx & 15) * 4;
        float4 q = *(const float4*)&Qp[(qt * 64 + r) * DH + cv];
        Qs[r * LDF + cv + 0] = f2tf(q.x * 0.125f);
        Qs[r * LDF + cv + 1] = f2tf(q.y * 0.125f);
        Qs[r * LDF + cv + 2] = f2tf(q.z * 0.125f);
        Qs[r * LDF + cv + 3] = f2tf(q.w * 0.125f);
    }

    float O[8][4];
    float mrow[2], lrow[2];
    #pragma unroll
    for (int nt = 0; nt < 8; nt++)
        #pragma unroll
        for (int i = 0; i < 4; i++) O[nt][i] = 0.f;
    mrow[0] = mrow[1] = -1e30f;
    lrow[0] = lrow[1] = 0.f;

    for (int kt = 0; kt < SS / 64; kt++) {
        __syncthreads();   // prior reads of Ks/Vs/Ps complete (also fences Q on iter 0)
        for (int idx = tid; idx < 64 * DH / 4; idx += 128) {
            int r = idx >> 4, cv = (idx & 15) * 4;
            float4 k4 = *(const float4*)&Kp[(kt * 64 + r) * DH + cv];
            Ks[r * LDF + cv + 0] = f2tf(k4.x);
            Ks[r * LDF + cv + 1] = f2tf(k4.y);
            Ks[r * LDF + cv + 2] = f2tf(k4.z);
            Ks[r * LDF + cv + 3] = f2tf(k4.w);
            float4 v4 = *(const float4*)&Vp[(kt * 64 + r) * DH + cv];
            Vs[r * LDF + cv + 0] = f2tf(v4.x);
            Vs[r * LDF + cv + 1] = f2tf(v4.y);
            Vs[r * LDF + cv + 2] = f2tf(v4.z);
            Vs[r * LDF + cv + 3] = f2tf(v4.w);
        }
        __syncthreads();

        // S = (Q*scale) @ K^T : m=16 (warp rows), n=64 (kv), k=64 (d)
        float S[8][4];
        #pragma unroll
        for (int nt = 0; nt < 8; nt++)
            #pragma unroll
            for (int i = 0; i < 4; i++) S[nt][i] = 0.f;

        #pragma unroll
        for (int ks = 0; ks < 8; ks++) {
            const int kk = ks * 8;
            unsigned af[4];
            int r = warp * 16 + (lane >> 2);
            af[0] = Qs[r * LDF + kk + (lane & 3)];
            af[1] = Qs[(r + 8) * LDF + kk + (lane & 3)];
            af[2] = Qs[r * LDF + kk + 4 + (lane & 3)];
            af[3] = Qs[(r + 8) * LDF + kk + 4 + (lane & 3)];
            #pragma unroll
            for (int nt = 0; nt < 8; nt++) {
                unsigned bf[2];
                int c = nt * 8 + (lane >> 2);           // kv index (n)
                bf[0] = Ks[c * LDF + kk + (lane & 3)];  // K[kv][d] = B[n][k]
                bf[1] = Ks[c * LDF + kk + 4 + (lane & 3)];
                mma8(S[nt], af, bf);
            }
        }

        // Online softmax. Row r owned by quad (lanes with same lane>>2);
        // halves: regs {0,1} = row lane>>2, regs {2,3} = row lane>>2 + 8.
        #pragma unroll
        for (int h2 = 0; h2 < 2; h2++) {
            float mx = -1e30f;
            #pragma unroll
            for (int nt = 0; nt < 8; nt++)
                mx = fmaxf(mx, fmaxf(S[nt][h2 * 2], S[nt][h2 * 2 + 1]));
            mx = fmaxf(mx, __shfl_xor_sync(0xffffffffu, mx, 1));
            mx = fmaxf(mx, __shfl_xor_sync(0xffffffffu, mx, 2));
            float mnew = fmaxf(mrow[h2], mx);
            float alpha = __expf(mrow[h2] - mnew);
            float sum = 0.f;
            int r = warp * 16 + (lane >> 2) + h2 * 8;
            #pragma unroll
            for (int nt = 0; nt < 8; nt++) {
                float p0 = __expf(S[nt][h2 * 2] - mnew);
                float p1 = __expf(S[nt][h2 * 2 + 1] - mnew);
                sum += p0 + p1;
                *(uint2*)&Ps[r * LDF + nt * 8 + (lane & 3) * 2] =
                    make_uint2(f2tf(p0), f2tf(p1));
            }
            sum += __shfl_xor_sync(0xffffffffu, sum, 1);
            sum += __shfl_xor_sync(0xffffffffu, sum, 2);
            lrow[h2] = lrow[h2] * alpha + sum;
            mrow[h2] = mnew;
            #pragma unroll
            for (int nt = 0; nt < 8; nt++) {
                O[nt][h2 * 2] *= alpha;
                O[nt][h2 * 2 + 1] *= alpha;
            }
        }
        __syncthreads();   // Ps visible to own warp's frag loads (and keeps tiles coherent)

        // O += P @ V : m=16, n=64 (d), k=64 (kv). B[n][k]=V[kv][d] -> Vs row-major as-is.
        #pragma unroll
        for (int ks = 0; ks < 8; ks++) {
            const int kk = ks * 8;
            unsigned af[4];
            int r = warp * 16 + (lane >> 2);
            af[0] = Ps[r * LDF + kk + (lane & 3)];
            af[1] = Ps[(r + 8) * LDF + kk + (lane & 3)];
            af[2] = Ps[r * LDF + kk + 4 + (lane & 3)];
            af[3] = Ps[(r + 8) * LDF + kk + 4 + (lane & 3)];
            #pragma unroll
            for (int nt = 0; nt < 8; nt++) {
                unsigned bf[2];
                int c = nt * 8 + (lane >> 2);                // d index (n)
                bf[0] = Vs[(kk + (lane & 3)) * LDF + c];     // V[kv][d] = B[n][k]
                bf[1] = Vs[(kk + 4 + (lane & 3)) * LDF + c];
                mma8(O[nt], af, bf);
            }
        }
    }

    // Normalize + store concat layout [B,S,H*64]
    const int b = bh >> 4, hh = bh & 15;
    #pragma unroll
    for (int h2 = 0; h2 < 2; h2++) {
        float inv = 1.f / lrow[h2];
        int s = qt * 64 + warp * 16 + (lane >> 2) + h2 * 8;
        float* base = &g_A[((size_t)(b * SS + s)) * DM + hh * DH];
        #pragma unroll
        for (int nt = 0; nt < 8; nt++) {
            int c = nt * 8 + (lane & 3) * 2;
            *(float2*)&base[c] = make_float2(O[nt][h2 * 2] * inv,
                                             O[nt][h2 * 2 + 1] * inv);
        }
    }
}

extern "C" void kernel_launch(void* const* d_in, const int* in_sizes, int n_in,
                              void* d_out, int out_size) {
    const float* x  = (const float*)d_in[0];
    const float* wq = (const float*)d_in[1];
    const float* wk = (const float*)d_in[2];
    const float* wv = (const float*)d_in[3];
    const float* wo = (const float*)d_in[4];
    const float* bo = (const float*)d_in[5];
    float* out = (float*)d_out;

    cudaFuncSetAttribute(flash_attn_tc,
                         cudaFuncAttributeMaxDynamicSharedMemorySize,
                         FA_SMEM_BYTES);

    dim3 gProj(DM / 128, MTOT / 128, 3);   // 8 x 32 x 3
    gemm_tc<0><<<gProj, 256>>>(x, wq, wk, wv, nullptr, nullptr);

    dim3 gAttn(SS / 64, BB * HH);          // 32 x 32
    flash_attn_tc<<<gAttn, 128, FA_SMEM_BYTES>>>();

    dim3 gOut(DM / 128, MTOT / 128);       // 8 x 32
    gemm_tc<1><<<gOut, 256>>>(nullptr, wo, nullptr, nullptr, bo, out);
}

// round 5
// speedup vs baseline: 4.6626x; 1.3431x over previous
#include <cuda_runtime.h>
#include <cuda_fp16.h>

#define BB 2
#define SS 2048
#define HH 16
#define DH 64
#define DM 1024
#define MTOT (BB*SS)   // 4096

// Scratch (device globals are the sanctioned scratch mechanism)
__device__ float g_Q[BB*HH*SS*DH];   // [B,H,S,64]
__device__ float g_K[BB*HH*SS*DH];
__device__ float g_V[BB*HH*SS*DH];
__device__ float g_A[MTOT*DM];       // attention concat output [B,S,1024]

// ---------------------------------------------------------------------------
// helpers
// ---------------------------------------------------------------------------
__device__ __forceinline__ unsigned f2tf(float f) {
    unsigned u;
    asm("cvt.rna.tf32.f32 %0, %1;" : "=r"(u) : "f"(f));
    return u;
}

__device__ __forceinline__ void mma8(float* d, const unsigned* a, const unsigned* b) {
    asm volatile(
        "mma.sync.aligned.m16n8k8.row.col.f32.tf32.tf32.f32 "
        "{%0,%1,%2,%3},{%4,%5,%6,%7},{%8,%9},{%0,%1,%2,%3};"
        : "+f"(d[0]), "+f"(d[1]), "+f"(d[2]), "+f"(d[3])
        : "r"(a[0]), "r"(a[1]), "r"(a[2]), "r"(a[3]), "r"(b[0]), "r"(b[1]));
}

__device__ __forceinline__ void mma16h(float* d, const unsigned* a, const unsigned* b) {
    asm volatile(
        "mma.sync.aligned.m16n8k16.row.col.f32.f16.f16.f32 "
        "{%0,%1,%2,%3},{%4,%5,%6,%7},{%8,%9},{%0,%1,%2,%3};"
        : "+f"(d[0]), "+f"(d[1]), "+f"(d[2]), "+f"(d[3])
        : "r"(a[0]), "r"(a[1]), "r"(a[2]), "r"(a[3]), "r"(b[0]), "r"(b[1]));
}

__device__ __forceinline__ unsigned sptr(const void* p) {
    return (unsigned)__cvta_generic_to_shared(p);
}

__device__ __forceinline__ void ldsm4(unsigned& r0, unsigned& r1, unsigned& r2,
                                      unsigned& r3, unsigned addr) {
    asm volatile("ldmatrix.sync.aligned.m8n8.x4.shared.b16 {%0,%1,%2,%3},[%4];"
                 : "=r"(r0), "=r"(r1), "=r"(r2), "=r"(r3) : "r"(addr));
}

__device__ __forceinline__ void ldsm4t(unsigned& r0, unsigned& r1, unsigned& r2,
                                       unsigned& r3, unsigned addr) {
    asm volatile("ldmatrix.sync.aligned.m8n8.x4.trans.shared.b16 {%0,%1,%2,%3},[%4];"
                 : "=r"(r0), "=r"(r1), "=r"(r2), "=r"(r3) : "r"(addr));
}

__device__ __forceinline__ unsigned h2u(__half2 h) {
    return *reinterpret_cast<unsigned*>(&h);
}

// ---------------------------------------------------------------------------
// Tensor-core tf32 GEMM: C = A @ B (+bias). 128x128x32 tiles, 256 thr, 8 warps.
// MODE 0: qkv (B by blockIdx.z, head-major store)  MODE 1: out (bias, row-major)
// ---------------------------------------------------------------------------
#define GLDA 36
#define GLDB 132

template<int MODE>
__global__ __launch_bounds__(256)
void gemm_tc(const float* __restrict__ Ain,
             const float* __restrict__ B0,
             const float* __restrict__ B1,
             const float* __restrict__ B2,
             const float* __restrict__ bias,
             float* __restrict__ outp) {
    __shared__ unsigned As[128 * GLDA];
    __shared__ unsigned Bs[32 * GLDB];

    const int tid = threadIdx.x, lane = tid & 31, warp = tid >> 5;
    const int wm = (warp & 1) * 64, wn = (warp >> 1) * 32;
    const int rowBase = blockIdx.y * 128, colBase = blockIdx.x * 128;

    const float* __restrict__ A = (MODE == 0) ? Ain : g_A;
    const float* __restrict__ B =
        (MODE == 0) ? (blockIdx.z == 0 ? B0 : blockIdx.z == 1 ? B1 : B2) : B0;

    float acc[4][4][4];
    #pragma unroll
    for (int mt = 0; mt < 4; mt++)
        #pragma unroll
        for (int nt = 0; nt < 4; nt++)
            #pragma unroll
            for (int i = 0; i < 4; i++) acc[mt][nt][i] = 0.f;

    for (int kb = 0; kb < DM; kb += 32) {
        #pragma unroll
        for (int it = 0; it < 4; it++) {
            int idx = tid + it * 256;
            int r = idx >> 3, cv = (idx & 7) * 4;
            float4 a = *(const float4*)&A[(size_t)(rowBase + r) * DM + kb + cv];
            As[r * GLDA + cv + 0] = f2tf(a.x);
            As[r * GLDA + cv + 1] = f2tf(a.y);
            As[r * GLDA + cv + 2] = f2tf(a.z);
            As[r * GLDA + cv + 3] = f2tf(a.w);
            int rb = idx >> 5, cb = (idx & 31) * 4;
            float4 b = *(const float4*)&B[(size_t)(kb + rb) * DM + colBase + cb];
            Bs[rb * GLDB + cb + 0] = f2tf(b.x);
            Bs[rb * GLDB + cb + 1] = f2tf(b.y);
            Bs[rb * GLDB + cb + 2] = f2tf(b.z);
            Bs[rb * GLDB + cb + 3] = f2tf(b.w);
        }
        __syncthreads();

        #pragma unroll
        for (int ks = 0; ks < 4; ks++) {
            const int kk = ks * 8;
            unsigned af[4][4], bf[4][2];
            #pragma unroll
            for (int mt = 0; mt < 4; mt++) {
                int r = wm + mt * 16 + (lane >> 2);
                af[mt][0] = As[r * GLDA + kk + (lane & 3)];
                af[mt][1] = As[(r + 8) * GLDA + kk + (lane & 3)];
                af[mt][2] = As[r * GLDA + kk + 4 + (lane & 3)];
                af[mt][3] = As[(r + 8) * GLDA + kk + 4 + (lane & 3)];
            }
            #pragma unroll
            for (int nt = 0; nt < 4; nt++) {
                int c = wn + nt * 8 + (lane >> 2);
                bf[nt][0] = Bs[(kk + (lane & 3)) * GLDB + c];
                bf[nt][1] = Bs[(kk + 4 + (lane & 3)) * GLDB + c];
            }
            #pragma unroll
            for (int mt = 0; mt < 4; mt++)
                #pragma unroll
                for (int nt = 0; nt < 4; nt++)
                    mma8(acc[mt][nt], af[mt], bf[nt]);
        }
        __syncthreads();
    }

    if (MODE == 0) {
        float* __restrict__ dst =
            (blockIdx.z == 0) ? g_Q : (blockIdx.z == 1) ? g_K : g_V;
        #pragma unroll
        for (int mt = 0; mt < 4; mt++)
            #pragma unroll
            for (int nt = 0; nt < 4; nt++) {
                int r0 = rowBase + wm + mt * 16 + (lane >> 2);
                int c0 = colBase + wn + nt * 8 + (lane & 3) * 2;
                int h = c0 >> 6, d = c0 & 63;
                int bb = r0 >> 11, s = r0 & 2047;
                float* p = &dst[(((size_t)(bb * HH + h) * SS) + s) * DH + d];
                *(float2*)p = make_float2(acc[mt][nt][0], acc[mt][nt][1]);
                float* p2 = &dst[(((size_t)(bb * HH + h) * SS) + s + 8) * DH + d];
                *(float2*)p2 = make_float2(acc[mt][nt][2], acc[mt][nt][3]);
            }
    } else {
        #pragma unroll
        for (int mt = 0; mt < 4; mt++)
            #pragma unroll
            for (int nt = 0; nt < 4; nt++) {
                int r0 = rowBase + wm + mt * 16 + (lane >> 2);
                int c0 = colBase + wn + nt * 8 + (lane & 3) * 2;
                float2 bi = *(const float2*)&bias[c0];
                *(float2*)&outp[(size_t)r0 * DM + c0] =
                    make_float2(acc[mt][nt][0] + bi.x, acc[mt][nt][1] + bi.y);
                *(float2*)&outp[(size_t)(r0 + 8) * DM + c0] =
                    make_float2(acc[mt][nt][2] + bi.x, acc[mt][nt][3] + bi.y);
            }
    }
}

// ---------------------------------------------------------------------------
// Flash attention, fp16 m16n8k16. BQ=128 (8 warps x 16 rows), BKT=64, d=64.
// P kept in registers (S C-frag -> A-frag). V consumed via ldmatrix.trans.
// Smem: Qh[128][72] Kh[64][72] Vh[64][72] halfs = 36 KB static.
// ---------------------------------------------------------------------------
#define LDH 72
#define BQF 128

__global__ __launch_bounds__(256)
void flash_attn_h() {
    __shared__ __half Qh[BQF * LDH];
    __shared__ __half Kh[64 * LDH];
    __shared__ __half Vh[64 * LDH];

    const int qt = blockIdx.x;   // 0..15
    const int bh = blockIdx.y;   // 0..31
    const float* __restrict__ Qp = g_Q + (size_t)bh * SS * DH;
    const float* __restrict__ Kp = g_K + (size_t)bh * SS * DH;
    const float* __restrict__ Vp = g_V + (size_t)bh * SS * DH;

    const int tid = threadIdx.x, lane = tid & 31, warp = tid >> 5;
    const int g = lane >> 3, rit = lane & 7;   // ldmatrix group / row-in-tile

    // Load Q tile (128 x 64), fold in 1/8 softmax scale.
    for (int idx = tid; idx < BQF * 16; idx += 256) {
        int r = idx >> 4, c = (idx & 15) * 4;
        float4 q = *(const float4*)&Qp[(qt * BQF + r) * DH + c];
        __half2 h0 = __floats2half2_rn(q.x * 0.125f, q.y * 0.125f);
        __half2 h1 = __floats2half2_rn(q.z * 0.125f, q.w * 0.125f);
        *(__half2*)&Qh[r * LDH + c]     = h0;
        *(__half2*)&Qh[r * LDH + c + 2] = h1;
    }

    float O[8][4];
    float mrow[2], lrow[2];
    #pragma unroll
    for (int nt = 0; nt < 8; nt++)
        #pragma unroll
        for (int i = 0; i < 4; i++) O[nt][i] = 0.f;
    mrow[0] = mrow[1] = -1e30f;
    lrow[0] = lrow[1] = 0.f;

    for (int kt = 0; kt < SS / 64; kt++) {
        __syncthreads();   // prior mma reads of Kh/Vh done (iter0: Qh stores fenced)
        for (int idx = tid; idx < 64 * 16; idx += 256) {
            int r = idx >> 4, c = (idx & 15) * 4;
            float4 k4 = *(const float4*)&Kp[(kt * 64 + r) * DH + c];
            *(__half2*)&Kh[r * LDH + c]     = __floats2half2_rn(k4.x, k4.y);
            *(__half2*)&Kh[r * LDH + c + 2] = __floats2half2_rn(k4.z, k4.w);
            float4 v4 = *(const float4*)&Vp[(kt * 64 + r) * DH + c];
            *(__half2*)&Vh[r * LDH + c]     = __floats2half2_rn(v4.x, v4.y);
            *(__half2*)&Vh[r * LDH + c + 2] = __floats2half2_rn(v4.z, v4.w);
        }
        __syncthreads();

        // S = (Q*scale) @ K^T : m=16, n=64 (kv), k=64 (d)
        float S[8][4];
        #pragma unroll
        for (int nt = 0; nt < 8; nt++)
            #pragma unroll
            for (int i = 0; i < 4; i++) S[nt][i] = 0.f;

        #pragma unroll
        for (int ks = 0; ks < 4; ks++) {
            const int kk = ks * 16;
            unsigned af[4];
            // A 16x16 at (rows warp*16, cols kk)
            ldsm4(af[0], af[1], af[2], af[3],
                  sptr(&Qh[(warp * 16 + (g & 1) * 8 + rit) * LDH + kk + (g >> 1) * 8]));
            #pragma unroll
            for (int nt2 = 0; nt2 < 4; nt2++) {
                unsigned bf[4];
                // b0/b1 for n-tiles 2*nt2, 2*nt2+1
                ldsm4(bf[0], bf[1], bf[2], bf[3],
                      sptr(&Kh[(nt2 * 16 + (g >> 1) * 8 + rit) * LDH + kk + (g & 1) * 8]));
                mma16h(S[nt2 * 2],     af, bf);
                mma16h(S[nt2 * 2 + 1], af, bf + 2);
            }
        }

        // Online softmax; P built in registers as fp16 A-fragments.
        unsigned Pf[4][4];   // [k-tile over kv][a0..a3]
        #pragma unroll
        for (int h2 = 0; h2 < 2; h2++) {
            float mx = -1e30f;
            #pragma unroll
            for (int nt = 0; nt < 8; nt++)
                mx = fmaxf(mx, fmaxf(S[nt][h2 * 2], S[nt][h2 * 2 + 1]));
            mx = fmaxf(mx, __shfl_xor_sync(0xffffffffu, mx, 1));
            mx = fmaxf(mx, __shfl_xor_sync(0xffffffffu, mx, 2));
            float mnew = fmaxf(mrow[h2], mx);
            float alpha = __expf(mrow[h2] - mnew);
            float sum = 0.f;
            #pragma unroll
            for (int nt = 0; nt < 8; nt++) {
                float p0 = __expf(S[nt][h2 * 2] - mnew);
                float p1 = __expf(S[nt][h2 * 2 + 1] - mnew);
                S[nt][h2 * 2] = p0;       // reuse S regs to hold P
                S[nt][h2 * 2 + 1] = p1;
                sum += p0 + p1;
            }
            sum += __shfl_xor_sync(0xffffffffu, sum, 1);
            sum += __shfl_xor_sync(0xffffffffu, sum, 2);
            lrow[h2] = lrow[h2] * alpha + sum;
            mrow[h2] = mnew;
            #pragma unroll
            for (int nt = 0; nt < 8; nt++) {
                O[nt][h2 * 2] *= alpha;
                O[nt][h2 * 2 + 1] *= alpha;
            }
        }
        // Pack: PV k-tile kt2 (16 kv) = S n-tiles 2kt2 (a0,a1) and 2kt2+1 (a2,a3)
        #pragma unroll
        for (int kt2 = 0; kt2 < 4; kt2++) {
            Pf[kt2][0] = h2u(__floats2half2_rn(S[kt2 * 2][0],     S[kt2 * 2][1]));
            Pf[kt2][1] = h2u(__floats2half2_rn(S[kt2 * 2][2],     S[kt2 * 2][3]));
            Pf[kt2][2] = h2u(__floats2half2_rn(S[kt2 * 2 + 1][0], S[kt2 * 2 + 1][1]));
            Pf[kt2][3] = h2u(__floats2half2_rn(S[kt2 * 2 + 1][2], S[kt2 * 2 + 1][3]));
        }

        // O += P @ V : m=16, n=64 (d), k=64 (kv). V via ldmatrix.trans.
        #pragma unroll
        for (int kt2 = 0; kt2 < 4; kt2++) {
            const int kk = kt2 * 16;
            #pragma unroll
            for (int nt2 = 0; nt2 < 4; nt2++) {
                unsigned bf[4];
                ldsm4t(bf[0], bf[1], bf[2], bf[3],
                       sptr(&Vh[(kk + (g & 1) * 8 + rit) * LDH + nt2 * 16 + (g >> 1) * 8]));
                mma16h(O[nt2 * 2],     Pf[kt2], bf);
                mma16h(O[nt2 * 2 + 1], Pf[kt2], bf + 2);
            }
        }
    }

    // Normalize + store concat layout [B,S,H*64]
    const int b = bh >> 4, hh = bh & 15;
    #pragma unroll
    for (int h2 = 0; h2 < 2; h2++) {
        float inv = 1.f / lrow[h2];
        int s = qt * BQF + warp * 16 + (lane >> 2) + h2 * 8;
        float* base = &g_A[((size_t)(b * SS + s)) * DM + hh * DH];
        #pragma unroll
        for (int nt = 0; nt < 8; nt++) {
            int c = nt * 8 + (lane & 3) * 2;
            *(float2*)&base[c] = make_float2(O[nt][h2 * 2] * inv,
                                             O[nt][h2 * 2 + 1] * inv);
        }
    }
}

extern "C" void kernel_launch(void* const* d_in, const int* in_sizes, int n_in,
                              void* d_out, int out_size) {
    const float* x  = (const float*)d_in[0];
    const float* wq = (const float*)d_in[1];
    const float* wk = (const float*)d_in[2];
    const float* wv = (const float*)d_in[3];
    const float* wo = (const float*)d_in[4];
    const float* bo = (const float*)d_in[5];
    float* out = (float*)d_out;

    dim3 gProj(DM / 128, MTOT / 128, 3);   // 8 x 32 x 3
    gemm_tc<0><<<gProj, 256>>>(x, wq, wk, wv, nullptr, nullptr);

    dim3 gAttn(SS / BQF, BB * HH);         // 16 x 32
    flash_attn_h<<<gAttn, 256>>>();

    dim3 gOut(DM / 128, MTOT / 128);       // 8 x 32
    gemm_tc<1><<<gOut, 256>>>(nullptr, wo, nullptr, nullptr, bo, out);
}

// round 6
// speedup vs baseline: 8.1886x; 1.7562x over previous
#include <cuda_runtime.h>
#include <cuda_fp16.h>

#define BB 2
#define SS 2048
#define HH 16
#define DH 64
#define DM 1024
#define MTOT (BB*SS)   // 4096

// fp16 scratch (device globals = sanctioned scratch)
__device__ __half g_xh[MTOT*DM];
__device__ __half g_wqh[DM*DM];       // pre-scaled by 0.125 (softmax scale)
__device__ __half g_wkh[DM*DM];
__device__ __half g_wvh[DM*DM];
__device__ __half g_woh[DM*DM];
__device__ __half g_Qh[BB*HH*SS*DH];  // [B,H,S,64]
__device__ __half g_Kh[BB*HH*SS*DH];
__device__ __half g_Vh[BB*HH*SS*DH];
__device__ __half g_Ah[MTOT*DM];      // attention concat output, fp16

// ---------------------------------------------------------------------------
// helpers
// ---------------------------------------------------------------------------
__device__ __forceinline__ void mma16h(float* d, const unsigned* a, const unsigned* b) {
    asm volatile(
        "mma.sync.aligned.m16n8k16.row.col.f32.f16.f16.f32 "
        "{%0,%1,%2,%3},{%4,%5,%6,%7},{%8,%9},{%0,%1,%2,%3};"
        : "+f"(d[0]), "+f"(d[1]), "+f"(d[2]), "+f"(d[3])
        : "r"(a[0]), "r"(a[1]), "r"(a[2]), "r"(a[3]), "r"(b[0]), "r"(b[1]));
}

__device__ __forceinline__ void ldsm4(unsigned& r0, unsigned& r1, unsigned& r2,
                                      unsigned& r3, unsigned addr) {
    asm volatile("ldmatrix.sync.aligned.m8n8.x4.shared.b16 {%0,%1,%2,%3},[%4];"
                 : "=r"(r0), "=r"(r1), "=r"(r2), "=r"(r3) : "r"(addr));
}

__device__ __forceinline__ void ldsm4t(unsigned& r0, unsigned& r1, unsigned& r2,
                                       unsigned& r3, unsigned addr) {
    asm volatile("ldmatrix.sync.aligned.m8n8.x4.trans.shared.b16 {%0,%1,%2,%3},[%4];"
                 : "=r"(r0), "=r"(r1), "=r"(r2), "=r"(r3) : "r"(addr));
}

__device__ __forceinline__ unsigned h2u(__half2 h) {
    return *reinterpret_cast<unsigned*>(&h);
}

// SW128 xor-swizzle on byte offsets (rows are exactly 128B)
__device__ __forceinline__ unsigned swz(unsigned o) {
    return o ^ ((o >> 3) & 0x70);
}

__device__ __forceinline__ void cpa16(unsigned dst, const void* src) {
    asm volatile("cp.async.cg.shared.global [%0], [%1], 16;" :: "r"(dst), "l"(src));
}
__device__ __forceinline__ void cp_commit() {
    asm volatile("cp.async.commit_group;");
}
template<int N>
__device__ __forceinline__ void cp_wait() {
    asm volatile("cp.async.wait_group %0;" :: "n"(N));
}

// ---------------------------------------------------------------------------
// fp32 -> fp16 converter (optionally scaled)
// ---------------------------------------------------------------------------
__global__ void conv_h(const float* __restrict__ src, __half* __restrict__ dst,
                       int n4, float scale) {
    int i = blockIdx.x * blockDim.x + threadIdx.x;
    if (i < n4) {
        float4 v = ((const float4*)src)[i];
        ((__half2*)dst)[i * 2]     = __floats2half2_rn(v.x * scale, v.y * scale);
        ((__half2*)dst)[i * 2 + 1] = __floats2half2_rn(v.z * scale, v.w * scale);
    }
}

// ---------------------------------------------------------------------------
// fp16 GEMM: 128x128 tile, BK=64, 256 thr / 8 warps (warp tile 64x32),
// cp.async double-buffered, SW128-swizzled smem (A:16KB, B:2x8KB halves).
// MODE 0: qkv  (A=g_xh, B by blockIdx.z, head-major half store to g_{Q,K,V}h)
// MODE 1: out  (A=g_Ah, B=g_woh, +bias, float store to outp)
// Smem: A[p] @ p*32768, B[p] @ 16384 + p*32768 ; total 64 KB dynamic.
// ---------------------------------------------------------------------------
#define HG_SMEM 65536

template<int MODE>
__global__ __launch_bounds__(256)
void hgemm(const float* __restrict__ bias, float* __restrict__ outp) {
    extern __shared__ __align__(128) char smc[];
    const unsigned smb = (unsigned)__cvta_generic_to_shared(smc);

    const int tid = threadIdx.x, lane = tid & 31, warp = tid >> 5;
    const int g = lane >> 3, rit = lane & 7;
    const int wm = (warp & 1) * 64, wn = (warp >> 1) * 32;
    const int rowBase = blockIdx.y * 128, colBase = blockIdx.x * 128;

    const __half* __restrict__ A = (MODE == 0) ? g_xh : g_Ah;
    const __half* __restrict__ Bm =
        (MODE == 0) ? (blockIdx.z == 0 ? g_wqh : blockIdx.z == 1 ? g_wkh : g_wvh)
                    : g_woh;

    float acc[4][4][4];
    #pragma unroll
    for (int mt = 0; mt < 4; mt++)
        #pragma unroll
        for (int nt = 0; nt < 4; nt++)
            #pragma unroll
            for (int i = 0; i < 4; i++) acc[mt][nt][i] = 0.f;

    // tile loader: A 128x64 halfs (8 granules/row), B 64x128 halfs (two 64-wide
    // swizzle tiles of 8KB each)
    auto loadTile = [&](int kb, int p) {
        unsigned bA = smb + p * 32768;
        unsigned bB = smb + 16384 + p * 32768;
        #pragma unroll
        for (int it = 0; it < 4; it++) {
            int idx = tid + it * 256;
            int r = idx >> 3, c8 = (idx & 7) * 8;
            cpa16(bA + swz(r * 128 + c8 * 2),
                  &A[(size_t)(rowBase + r) * DM + kb + c8]);
            int k = idx >> 4, nc = (idx & 15) * 8;
            cpa16(bB + (nc >> 6) * 8192 + swz(k * 128 + (nc & 63) * 2),
                  &Bm[(size_t)(kb + k) * DM + colBase + nc]);
        }
    };

    loadTile(0, 0);
    cp_commit();

    for (int t = 0; t < 16; t++) {
        if (t + 1 < 16) { loadTile((t + 1) * 64, (t + 1) & 1); cp_commit(); }
        if (t + 1 < 16) cp_wait<1>(); else cp_wait<0>();
        __syncthreads();

        unsigned bA = smb + (t & 1) * 32768;
        unsigned bB = smb + 16384 + (t & 1) * 32768;

        #pragma unroll
        for (int ks = 0; ks < 4; ks++) {
            const int kk = ks * 16;
            unsigned af[4][4];
            #pragma unroll
            for (int mt = 0; mt < 4; mt++) {
                int r = wm + mt * 16 + (g & 1) * 8 + rit;
                ldsm4(af[mt][0], af[mt][1], af[mt][2], af[mt][3],
                      bA + swz(r * 128 + (kk + (g >> 1) * 8) * 2));
            }
            #pragma unroll
            for (int nt2 = 0; nt2 < 2; nt2++) {
                int nloc = wn + nt2 * 16;
                unsigned bf[4];
                int krow = kk + (g & 1) * 8 + rit;
                ldsm4t(bf[0], bf[1], bf[2], bf[3],
                       bB + (nloc >> 6) * 8192 +
                       swz(krow * 128 + ((nloc & 63) + (g >> 1) * 8) * 2));
                #pragma unroll
                for (int mt = 0; mt < 4; mt++) {
                    mma16h(acc[mt][nt2 * 2],     af[mt], bf);
                    mma16h(acc[mt][nt2 * 2 + 1], af[mt], bf + 2);
                }
            }
        }
        __syncthreads();
    }

    if (MODE == 0) {
        __half* __restrict__ dst =
            (blockIdx.z == 0) ? g_Qh : (blockIdx.z == 1) ? g_Kh : g_Vh;
        #pragma unroll
        for (int mt = 0; mt < 4; mt++)
            #pragma unroll
            for (int nt = 0; nt < 4; nt++) {
                int r0 = rowBase + wm + mt * 16 + (lane >> 2);
                int c0 = colBase + wn + nt * 8 + (lane & 3) * 2;
                int h = c0 >> 6, d = c0 & 63;
                int bb = r0 >> 11, s = r0 & 2047;
                *(__half2*)&dst[(((size_t)(bb * HH + h) * SS) + s) * DH + d] =
                    __floats2half2_rn(acc[mt][nt][0], acc[mt][nt][1]);
                *(__half2*)&dst[(((size_t)(bb * HH + h) * SS) + s + 8) * DH + d] =
                    __floats2half2_rn(acc[mt][nt][2], acc[mt][nt][3]);
            }
    } else {
        #pragma unroll
        for (int mt = 0; mt < 4; mt++)
            #pragma unroll
            for (int nt = 0; nt < 4; nt++) {
                int r0 = rowBase + wm + mt * 16 + (lane >> 2);
                int c0 = colBase + wn + nt * 8 + (lane & 3) * 2;
                float2 bi = *(const float2*)&bias[c0];
                *(float2*)&outp[(size_t)r0 * DM + c0] =
                    make_float2(acc[mt][nt][0] + bi.x, acc[mt][nt][1] + bi.y);
                *(float2*)&outp[(size_t)(r0 + 8) * DM + c0] =
                    make_float2(acc[mt][nt][2] + bi.x, acc[mt][nt][3] + bi.y);
            }
    }
}

// ---------------------------------------------------------------------------
// Flash attention, fp16 in/out, cp.async K/V double-buffer.
// BQ=128 (8 warps x 16 rows), BKT=64, d=64. P in registers.
// Smem: Q 16KB @0 ; K[p] @16384+p*16384 ; V[p] = K[p]+8192. Total 48KB dynamic.
// ---------------------------------------------------------------------------
#define FA_SMEM 49152

__global__ __launch_bounds__(256)
void flash_h() {
    extern __shared__ __align__(128) char smc[];
    const unsigned smQ = (unsigned)__cvta_generic_to_shared(smc);

    const int qt = blockIdx.x;   // 0..15
    const int bh = blockIdx.y;   // 0..31
    const __half* __restrict__ Qp = g_Qh + (size_t)bh * SS * DH;
    const __half* __restrict__ Kp = g_Kh + (size_t)bh * SS * DH;
    const __half* __restrict__ Vp = g_Vh + (size_t)bh * SS * DH;

    const int tid = threadIdx.x, lane = tid & 31, warp = tid >> 5;
    const int g = lane >> 3, rit = lane & 7;

    // Q tile: 128 rows x 64 halfs (Q already carries the 0.125 scale via wq)
    #pragma unroll
    for (int it = 0; it < 4; it++) {
        int idx = tid + it * 256;
        int r = idx >> 3, c8 = (idx & 7) * 8;
        cpa16(smQ + swz(r * 128 + c8 * 2), &Qp[(size_t)(qt * 128 + r) * DH + c8]);
    }
    // K/V tile 0
    {
        unsigned bK = smQ + 16384, bV = bK + 8192;
        #pragma unroll
        for (int it = 0; it < 2; it++) {
            int idx = tid + it * 256;
            int r = idx >> 3, c8 = (idx & 7) * 8;
            cpa16(bK + swz(r * 128 + c8 * 2), &Kp[(size_t)r * DH + c8]);
            cpa16(bV + swz(r * 128 + c8 * 2), &Vp[(size_t)r * DH + c8]);
        }
    }
    cp_commit();

    float O[8][4];
    float mrow[2], lrow[2];
    #pragma unroll
    for (int nt = 0; nt < 8; nt++)
        #pragma unroll
        for (int i = 0; i < 4; i++) O[nt][i] = 0.f;
    mrow[0] = mrow[1] = -1e30f;
    lrow[0] = lrow[1] = 0.f;

    for (int kt = 0; kt < SS / 64; kt++) {
        if (kt + 1 < SS / 64) {
            unsigned bK = smQ + 16384 + ((kt + 1) & 1) * 16384, bV = bK + 8192;
            #pragma unroll
            for (int it = 0; it < 2; it++) {
                int idx = tid + it * 256;
                int r = idx >> 3, c8 = (idx & 7) * 8;
                cpa16(bK + swz(r * 128 + c8 * 2),
                      &Kp[(size_t)((kt + 1) * 64 + r) * DH + c8]);
                cpa16(bV + swz(r * 128 + c8 * 2),
                      &Vp[(size_t)((kt + 1) * 64 + r) * DH + c8]);
            }
            cp_commit();
            cp_wait<1>();
        } else {
            cp_wait<0>();
        }
        __syncthreads();

        unsigned bK = smQ + 16384 + (kt & 1) * 16384, bV = bK + 8192;

        // S = Q @ K^T : m=16, n=64 (kv), k=64 (d). K stored [kv][d] = [n][k].
        float S[8][4];
        #pragma unroll
        for (int nt = 0; nt < 8; nt++)
            #pragma unroll
            for (int i = 0; i < 4; i++) S[nt][i] = 0.f;

        #pragma unroll
        for (int ks = 0; ks < 4; ks++) {
            const int kk = ks * 16;
            unsigned af[4];
            ldsm4(af[0], af[1], af[2], af[3],
                  smQ + swz((warp * 16 + (g & 1) * 8 + rit) * 128 +
                            (kk + (g >> 1) * 8) * 2));
            #pragma unroll
            for (int nt2 = 0; nt2 < 4; nt2++) {
                unsigned bf[4];
                ldsm4(bf[0], bf[1], bf[2], bf[3],
                      bK + swz((nt2 * 16 + (g >> 1) * 8 + rit) * 128 +
                               (kk + (g & 1) * 8) * 2));
                mma16h(S[nt2 * 2],     af, bf);
                mma16h(S[nt2 * 2 + 1], af, bf + 2);
            }
        }

        // Online softmax; P packed to fp16 A-fragments in registers.
        unsigned Pf[4][4];
        #pragma unroll
        for (int h2 = 0; h2 < 2; h2++) {
            float mx = -1e30f;
            #pragma unroll
            for (int nt = 0; nt < 8; nt++)
                mx = fmaxf(mx, fmaxf(S[nt][h2 * 2], S[nt][h2 * 2 + 1]));
            mx = fmaxf(mx, __shfl_xor_sync(0xffffffffu, mx, 1));
            mx = fmaxf(mx, __shfl_xor_sync(0xffffffffu, mx, 2));
            float mnew = fmaxf(mrow[h2], mx);
            float alpha = __expf(mrow[h2] - mnew);
            float sum = 0.f;
            #pragma unroll
            for (int nt = 0; nt < 8; nt++) {
                float p0 = __expf(S[nt][h2 * 2] - mnew);
                float p1 = __expf(S[nt][h2 * 2 + 1] - mnew);
                S[nt][h2 * 2] = p0;
                S[nt][h2 * 2 + 1] = p1;
                sum += p0 + p1;
            }
            sum += __shfl_xor_sync(0xffffffffu, sum, 1);
            sum += __shfl_xor_sync(0xffffffffu, sum, 2);
            lrow[h2] = lrow[h2] * alpha + sum;
            mrow[h2] = mnew;
            #pragma unroll
            for (int nt = 0; nt < 8; nt++) {
                O[nt][h2 * 2] *= alpha;
                O[nt][h2 * 2 + 1] *= alpha;
            }
        }
        #pragma unroll
        for (int kt2 = 0; kt2 < 4; kt2++) {
            Pf[kt2][0] = h2u(__floats2half2_rn(S[kt2 * 2][0],     S[kt2 * 2][1]));
            Pf[kt2][1] = h2u(__floats2half2_rn(S[kt2 * 2][2],     S[kt2 * 2][3]));
            Pf[kt2][2] = h2u(__floats2half2_rn(S[kt2 * 2 + 1][0], S[kt2 * 2 + 1][1]));
            Pf[kt2][3] = h2u(__floats2half2_rn(S[kt2 * 2 + 1][2], S[kt2 * 2 + 1][3]));
        }

        // O += P @ V : V stored [kv][d], consumed via ldmatrix.trans.
        #pragma unroll
        for (int kt2 = 0; kt2 < 4; kt2++) {
            const int kk = kt2 * 16;
            #pragma unroll
            for (int nt2 = 0; nt2 < 4; nt2++) {
                unsigned bf[4];
                ldsm4t(bf[0], bf[1], bf[2], bf[3],
                       bV + swz((kk + (g & 1) * 8 + rit) * 128 +
                                (nt2 * 16 + (g >> 1) * 8) * 2));
                mma16h(O[nt2 * 2],     Pf[kt2], bf);
                mma16h(O[nt2 * 2 + 1], Pf[kt2], bf + 2);
            }
        }
        __syncthreads();
    }

    // Normalize + store concat layout [B,S,H*64] as fp16
    const int b = bh >> 4, hh = bh & 15;
    #pragma unroll
    for (int h2 = 0; h2 < 2; h2++) {
        float inv = 1.f / lrow[h2];
        int s = qt * 128 + warp * 16 + (lane >> 2) + h2 * 8;
        __half* base = &g_Ah[((size_t)(b * SS + s)) * DM + hh * DH];
        #pragma unroll
        for (int nt = 0; nt < 8; nt++) {
            int c = nt * 8 + (lane & 3) * 2;
            *(__half2*)&base[c] =
                __floats2half2_rn(O[nt][h2 * 2] * inv, O[nt][h2 * 2 + 1] * inv);
        }
    }
}

extern "C" void kernel_launch(void* const* d_in, const int* in_sizes, int n_in,
                              void* d_out, int out_size) {
    const float* x  = (const float*)d_in[0];
    const float* wq = (const float*)d_in[1];
    const float* wk = (const float*)d_in[2];
    const float* wv = (const float*)d_in[3];
    const float* wo = (const float*)d_in[4];
    const float* bo = (const float*)d_in[5];
    float* out = (float*)d_out;

    // host-side attribute sets: no alloc, no sync, capture-safe
    cudaFuncSetAttribute(hgemm<0>, cudaFuncAttributeMaxDynamicSharedMemorySize, HG_SMEM);
    cudaFuncSetAttribute(hgemm<1>, cudaFuncAttributeMaxDynamicSharedMemorySize, HG_SMEM);
    cudaFuncSetAttribute(flash_h,  cudaFuncAttributeMaxDynamicSharedMemorySize, FA_SMEM);

    __half *p_xh, *p_wqh, *p_wkh, *p_wvh, *p_woh;
    cudaGetSymbolAddress((void**)&p_xh,  g_xh);
    cudaGetSymbolAddress((void**)&p_wqh, g_wqh);
    cudaGetSymbolAddress((void**)&p_wkh, g_wkh);
    cudaGetSymbolAddress((void**)&p_wvh, g_wvh);
    cudaGetSymbolAddress((void**)&p_woh, g_woh);

    conv_h<<<(MTOT*DM/4 + 255)/256, 256>>>(x,  p_xh,  MTOT*DM/4, 1.f);
    conv_h<<<(DM*DM/4 + 255)/256, 256>>>(wq, p_wqh, DM*DM/4, 0.125f);
    conv_h<<<(DM*DM/4 + 255)/256, 256>>>(wk, p_wkh, DM*DM/4, 1.f);
    conv_h<<<(DM*DM/4 + 255)/256, 256>>>(wv, p_wvh, DM*DM/4, 1.f);
    conv_h<<<(DM*DM/4 + 255)/256, 256>>>(wo, p_woh, DM*DM/4, 1.f);

    dim3 gProj(DM / 128, MTOT / 128, 3);   // 8 x 32 x 3
    hgemm<0><<<gProj, 256, HG_SMEM>>>(nullptr, nullptr);

    dim3 gAttn(SS / 128, BB * HH);         // 16 x 32
    flash_h<<<gAttn, 256, FA_SMEM>>>();

    dim3 gOut(DM / 128, MTOT / 128);       // 8 x 32
    hgemm<1><<<gOut, 256, HG_SMEM>>>(bo, out);
}